// round 10
// baseline (speedup 1.0000x reference)
#include <cuda_runtime.h>
#include <math.h>

#define BB 64
#define SS 512
#define HID 40
#define HEADS 4
#define DH 10
#define INTER 20
#define TT (BB*SS)
#define NBH (BB*HEADS)     // 256
#define KHALF (SS/2)       // 256

typedef unsigned long long u64;

// scratch (allocation-free rule: __device__ globals)
// q,k,v,pacc all TRANSPOSED: [bh][d][s]
__device__ __align__(16) float g_q[NBH*DH*SS];
__device__ __align__(16) float g_k[NBH*DH*SS];
__device__ __align__(16) float g_v[NBH*DH*SS];
__device__ __align__(16) float g_pacc[2*NBH*DH*SS];  // [kh][bh][d][s]
__device__ __align__(16) float g_pl[2*NBH*SS];       // [kh][bh][s]

__device__ __forceinline__ float ex2(float x){
    float y; asm("ex2.approx.f32 %0, %1;" : "=f"(y) : "f"(x)); return y;
}
__device__ __forceinline__ u64 pk2(float x, float y){
    u64 r; asm("mov.b64 %0, {%1, %2};" : "=l"(r) : "f"(x), "f"(y)); return r;
}
__device__ __forceinline__ float2 upk2(u64 a){
    float2 r; asm("mov.b64 {%0, %1}, %2;" : "=f"(r.x), "=f"(r.y) : "l"(a)); return r;
}
__device__ __forceinline__ u64 fma2(u64 a, u64 b, u64 c){
    u64 d; asm("fma.rn.f32x2 %0, %1, %2, %3;" : "=l"(d) : "l"(a), "l"(b), "l"(c)); return d;
}
__device__ __forceinline__ u64 add2(u64 a, u64 b){
    u64 d; asm("add.rn.f32x2 %0, %1, %2;" : "=l"(d) : "l"(a), "l"(b)); return d;
}

// ---------------- Kernel 1: LN1 + QKV projection (warp-uniform weights) ----------------
// block = 128 = 4 warps; lane = token (32 tokens/block); warp w computes outputs [30w,30w+30).
__global__ void __launch_bounds__(128) k_ln_qkv(
    const float* __restrict__ x,
    const float* __restrict__ g1, const float* __restrict__ b1,
    const float* __restrict__ Wq, const float* __restrict__ bq,
    const float* __restrict__ Wk, const float* __restrict__ bk,
    const float* __restrict__ Wv, const float* __restrict__ bv)
{
    __shared__ __align__(16) float Ws[HID*3*HID];   // [i][o]: 0-39 q, 40-79 k, 80-119 v
    __shared__ __align__(16) float bs[3*HID];
    __shared__ __align__(16) float xs[32*41];       // stride 41: lane-conflict-free
    __shared__ __align__(16) u64  hs[32*41];        // packed (h,h), stride 41 u64
    __shared__ float g1s[HID], b1s_[HID];

    const int tid  = threadIdx.x;
    const int w    = tid >> 5;
    const int lane = tid & 31;
    const int t0   = blockIdx.x * 32;

    for (int idx = tid; idx < HID*HID; idx += 128) {
        int i = idx / HID, o = idx % HID;
        Ws[i*120 + o]      = Wq[idx];
        Ws[i*120 + 40 + o] = Wk[idx];
        Ws[i*120 + 80 + o] = Wv[idx];
    }
    if (tid < HID) {
        bs[tid] = bq[tid]; bs[40+tid] = bk[tid]; bs[80+tid] = bv[tid];
        g1s[tid] = g1[tid]; b1s_[tid] = b1[tid];
    }
    for (int idx = tid; idx < 32*HID; idx += 128)
        xs[(idx/HID)*41 + (idx%HID)] = x[(size_t)t0*HID + idx];
    __syncthreads();

    const int tok = lane;
    const int b = blockIdx.x >> 4;
    const int s = ((blockIdx.x & 15) << 5) + lane;

    // LN stats (single pass, scalar conflict-free reads)
    float s1 = 0.f, s2 = 0.f;
#pragma unroll
    for (int i = 0; i < HID; i++) {
        float v = xs[tok*41 + i];
        s1 += v; s2 += v*v;
    }
    float mu = s1 * (1.f/HID);
    float var = s2 * (1.f/HID) - mu*mu;
    float rs = rsqrtf(var + 1e-5f);

    // warp w normalizes elements [10w,10w+10) of its lane's token
#pragma unroll
    for (int i = w*10; i < w*10 + 10; i++) {
        float hv = (xs[tok*41 + i] - mu)*rs*g1s[i] + b1s_[i];
        hs[tok*41 + i] = pk2(hv, hv);
    }
    __syncthreads();

    const int base = w * 30;
    u64 acc[15];
#pragma unroll
    for (int j = 0; j < 15; j++) acc[j] = *(const u64*)&bs[base + 2*j];
#pragma unroll
    for (int i = 0; i < HID; i++) {
        u64 h2 = hs[tok*41 + i];
        const u64* wr = (const u64*)&Ws[i*120 + base];   // uniform -> broadcast
#pragma unroll
        for (int j = 0; j < 15; j++) acc[j] = fma2(h2, wr[j], acc[j]);
    }
    // transposed stores: lane-coalesced scalar STG
#pragma unroll
    for (int j = 0; j < 15; j++) {
        float2 v = upk2(acc[j]);
        int o = base + 2*j;
#pragma unroll
        for (int e = 0; e < 2; e++) {
            int oo = o + e;
            float val = e ? v.y : v.x;
            float* dst = (oo < 40) ? g_q : (oo < 80) ? g_k : g_v;
            int r = oo % 40;
            int hd = r / DH, d = r % DH;
            dst[(((size_t)b*HEADS + hd)*DH + d)*SS + s] = val;
        }
    }
}

// ---------------- Kernel 2: attention, split-K, packed 2-keys-per-f32x2 ----------------
// grid = NBH*4 (bh, qh, kh); block 128; thread = 2 queries; K/V transposed in smem.
__global__ void __launch_bounds__(128) k_attn()
{
    __shared__ __align__(16) float ks[DH*KHALF];   // [d][s]
    __shared__ __align__(16) float vs[DH*KHALF];

    const int tid = threadIdx.x;
    const int blk = blockIdx.x;
    const int kh  = blk & 1;
    const int qh  = (blk >> 1) & 1;
    const int bh  = blk >> 2;

    const float* kg = g_k + (size_t)bh*DH*SS + kh*KHALF;
    const float* vg = g_v + (size_t)bh*DH*SS + kh*KHALF;
#pragma unroll
    for (int i = tid; i < DH*KHALF/4; i += 128) {
        int r = i >> 6, c = i & 63;   // 64 float4 per 256-float row
        ((float4*)ks)[r*64 + c] = ((const float4*)(kg + (size_t)r*SS))[c];
        ((float4*)vs)[r*64 + c] = ((const float4*)(vg + (size_t)r*SS))[c];
    }

    const int qA = qh*256 + tid;
    const int qB = qA + 128;
    const float scale = 0.316227766016838f * 1.44269504088896f; // 1/sqrt(DH)*log2e
    u64 qa2[DH], qb2[DH];
#pragma unroll
    for (int d = 0; d < DH; d++) {
        float a = g_q[((size_t)bh*DH + d)*SS + qA] * scale;   // coalesced
        float bq_ = g_q[((size_t)bh*DH + d)*SS + qB] * scale;
        qa2[d] = pk2(a, a);
        qb2[d] = pk2(bq_, bq_);
    }
    __syncthreads();

    const u64* ksu = (const u64*)ks;   // [d][s2] : u64 = 2 adjacent keys
    const u64* vsu = (const u64*)vs;

    u64 lA2 = 0ULL, lB2 = 0ULL;
    u64 aA[DH], aB[DH];
#pragma unroll
    for (int d = 0; d < DH; d++) { aA[d] = 0ULL; aB[d] = 0ULL; }

#pragma unroll 4
    for (int s2 = 0; s2 < KHALF/2; s2++) {
        u64 dA = 0ULL, dB = 0ULL;
#pragma unroll
        for (int d = 0; d < DH; d++) {
            u64 kp = ksu[d*(KHALF/2) + s2];    // uniform -> broadcast
            dA = fma2(qa2[d], kp, dA);
            dB = fma2(qb2[d], kp, dB);
        }
        float2 fa = upk2(dA);
        float2 fb = upk2(dB);
        u64 pA = pk2(ex2(fa.x), ex2(fa.y));    // scores tiny: no max subtraction
        u64 pB = pk2(ex2(fb.x), ex2(fb.y));
        lA2 = add2(lA2, pA);
        lB2 = add2(lB2, pB);
#pragma unroll
        for (int d = 0; d < DH; d++) {
            u64 vp = vsu[d*(KHALF/2) + s2];
            aA[d] = fma2(pA, vp, aA[d]);
            aB[d] = fma2(pB, vp, aB[d]);
        }
    }

    {
        float2 l = upk2(lA2);
        g_pl[((size_t)kh*NBH + bh)*SS + qA] = l.x + l.y;
#pragma unroll
        for (int d = 0; d < DH; d++) {
            float2 f = upk2(aA[d]);
            g_pacc[(((size_t)kh*NBH + bh)*DH + d)*SS + qA] = f.x + f.y;  // coalesced
        }
    }
    {
        float2 l = upk2(lB2);
        g_pl[((size_t)kh*NBH + bh)*SS + qB] = l.x + l.y;
#pragma unroll
        for (int d = 0; d < DH; d++) {
            float2 f = upk2(aB[d]);
            g_pacc[(((size_t)kh*NBH + bh)*DH + d)*SS + qB] = f.x + f.y;
        }
    }
}

// ---------------- Kernel 3: combine + Wo + residual + LN2 + FFN + residual ----------------
// block 128 = 4 warps; lane = token (32 tokens); warp w computes output slice [10w,10w+10).
__global__ void __launch_bounds__(128) k_out_ffn(
    const float* __restrict__ x,
    const float* __restrict__ Wo, const float* __restrict__ bo,
    const float* __restrict__ g2, const float* __restrict__ b2g,
    const float* __restrict__ W1, const float* __restrict__ b1f,
    const float* __restrict__ W2, const float* __restrict__ b2f,
    float* __restrict__ out)
{
    __shared__ __align__(16) float Wos[HID*HID];
    __shared__ __align__(16) float W1s[HID*INTER];
    __shared__ __align__(16) float W2s[INTER*HID];
    __shared__ __align__(16) u64  cs[32*41];     // packed (ctx,ctx), stride 41
    __shared__ __align__(16) float ao_s[32*41];  // stride 41 (scalar LN reads)
    __shared__ __align__(16) u64  h2s[32*41];    // packed (h2,h2)
    __shared__ __align__(16) float h2f[32*41];   // scalar copy for W1 GEMM
    __shared__ __align__(16) float it_s[32*21];  // stride 21
    __shared__ float bos[HID], b1s[INTER], b2s[HID], g2s[HID], b2gs[HID];

    const int tid  = threadIdx.x;
    const int w    = tid >> 5;
    const int lane = tid & 31;

    for (int i = tid; i < HID*HID; i += 128)   Wos[i] = Wo[i];
    for (int i = tid; i < HID*INTER; i += 128) W1s[i] = W1[i];
    for (int i = tid; i < INTER*HID; i += 128) W2s[i] = W2[i];
    if (tid < HID)   { bos[tid] = bo[tid]; b2s[tid] = b2f[tid]; g2s[tid] = g2[tid]; b2gs[tid] = b2g[tid]; }
    if (tid < INTER) { b1s[tid] = b1f[tid]; }

    const int tok = lane;
    const int t = blockIdx.x*32 + lane;
    const int b = blockIdx.x >> 4;
    const int s = ((blockIdx.x & 15) << 5) + lane;

    // combine split-K partials: warp w handles head w for its lane's token
    {
        const int bh = b*HEADS + w;
        float l = g_pl[(size_t)bh*SS + s] + g_pl[((size_t)NBH + bh)*SS + s];
        float inv = 1.f / l;
#pragma unroll
        for (int d = 0; d < DH; d++) {
            float p0 = g_pacc[((size_t)bh*DH + d)*SS + s];                   // coalesced
            float p1 = g_pacc[(((size_t)NBH + bh)*DH + d)*SS + s];
            float c = (p0 + p1) * inv;
            cs[tok*41 + w*DH + d] = pk2(c, c);
        }
    }
    __syncthreads();

    // ao[base..base+10) = ctx @ Wo + bo + x
    const int base = w * 10;
    u64 acc[5];
#pragma unroll
    for (int j = 0; j < 5; j++) acc[j] = *(const u64*)&bos[base + 2*j];
#pragma unroll
    for (int i = 0; i < HID; i++) {
        u64 c2 = cs[tok*41 + i];
        const u64* wr = (const u64*)&Wos[i*HID + base];   // uniform -> broadcast
#pragma unroll
        for (int j = 0; j < 5; j++) acc[j] = fma2(c2, wr[j], acc[j]);
    }
    float aoc[10];
#pragma unroll
    for (int j = 0; j < 5; j++) {
        float2 v = upk2(acc[j]);
        float2 xv = *(const float2*)&x[(size_t)t*HID + base + 2*j];
        aoc[2*j]   = v.x + xv.x;
        aoc[2*j+1] = v.y + xv.y;
        ao_s[tok*41 + base + 2*j]   = aoc[2*j];
        ao_s[tok*41 + base + 2*j+1] = aoc[2*j+1];
    }
    __syncthreads();

    // LN2 (single pass, scalar conflict-free)
    float s1 = 0.f, s2 = 0.f;
#pragma unroll
    for (int i = 0; i < HID; i++) {
        float v = ao_s[tok*41 + i];
        s1 += v; s2 += v*v;
    }
    float mu = s1 * (1.f/HID);
    float var = s2 * (1.f/HID) - mu*mu;
    float rs = rsqrtf(var + 1e-5f);
#pragma unroll
    for (int i = base; i < base + 10; i++) {
        float hv = (ao_s[tok*41 + i] - mu)*rs*g2s[i] + b2gs[i];
        h2s[tok*41 + i] = pk2(hv, hv);
        h2f[tok*41 + i] = hv;
    }
    __syncthreads();

    // inter[5w..5w+5) = gelu(h2 @ W1 + b1)
    {
        const int ibase = w * 5;
        float it[5];
#pragma unroll
        for (int o = 0; o < 5; o++) it[o] = b1s[ibase + o];
#pragma unroll
        for (int i = 0; i < HID; i++) {
            float hi = h2f[tok*41 + i];
            const float* wr = &W1s[i*INTER + ibase];      // uniform -> broadcast
#pragma unroll
            for (int o = 0; o < 5; o++) it[o] = fmaf(hi, wr[o], it[o]);
        }
#pragma unroll
        for (int o = 0; o < 5; o++) {
            float z = it[o];
            it_s[tok*21 + ibase + o] = 0.5f * z * (1.f + erff(z * 0.70710678118654752f));
        }
    }
    __syncthreads();

    // out[base..base+10) = inter @ W2 + b2 + ao
    u64 acc2[5];
#pragma unroll
    for (int j = 0; j < 5; j++) acc2[j] = *(const u64*)&b2s[base + 2*j];
#pragma unroll
    for (int i = 0; i < INTER; i++) {
        float iv = it_s[tok*21 + i];
        u64 i2 = pk2(iv, iv);
        const u64* wr = (const u64*)&W2s[i*HID + base];   // uniform -> broadcast
#pragma unroll
        for (int j = 0; j < 5; j++) acc2[j] = fma2(i2, wr[j], acc2[j]);
    }
#pragma unroll
    for (int j = 0; j < 5; j++) {
        float2 v = upk2(acc2[j]);
        float2 o; o.x = v.x + aoc[2*j]; o.y = v.y + aoc[2*j+1];
        *(float2*)&out[(size_t)t*HID + base + 2*j] = o;
    }
}

extern "C" void kernel_launch(void* const* d_in, const int* in_sizes, int n_in,
                              void* d_out, int out_size)
{
    const float* x    = (const float*)d_in[0];
    const float* ln1g = (const float*)d_in[1];
    const float* ln1b = (const float*)d_in[2];
    const float* Wq   = (const float*)d_in[3];
    const float* bq   = (const float*)d_in[4];
    const float* Wk   = (const float*)d_in[5];
    const float* bk   = (const float*)d_in[6];
    const float* Wv   = (const float*)d_in[7];
    const float* bv   = (const float*)d_in[8];
    const float* Wo   = (const float*)d_in[9];
    const float* bo   = (const float*)d_in[10];
    const float* ln2g = (const float*)d_in[11];
    const float* ln2b = (const float*)d_in[12];
    const float* W1   = (const float*)d_in[13];
    const float* b1   = (const float*)d_in[14];
    const float* W2   = (const float*)d_in[15];
    const float* b2   = (const float*)d_in[16];
    float* out = (float*)d_out;

    k_ln_qkv<<<TT/32, 128>>>(x, ln1g, ln1b, Wq, bq, Wk, bk, Wv, bv);
    k_attn<<<NBH*4, 128>>>();
    k_out_ffn<<<TT/32, 128>>>(x, Wo, bo, ln2g, ln2b, W1, b1, W2, b2, out);
}

// round 12
// speedup vs baseline: 1.4632x; 1.4632x over previous
#include <cuda_runtime.h>
#include <math.h>

#define BB 64
#define SS 512
#define HID 40
#define HEADS 4
#define DH 10
#define INTER 20
#define TT (BB*SS)
#define NBH (BB*HEADS)     // 256
#define KHALF (SS/2)       // 256

typedef unsigned long long u64;

// scratch (allocation-free rule: __device__ globals)
// q,k,v layout [bh][s][dh]; pacc [kh][bh][s][dh]
__device__ __align__(16) float g_q[NBH*SS*DH];
__device__ __align__(16) float g_k[NBH*SS*DH];
__device__ __align__(16) float g_v[NBH*SS*DH];
__device__ __align__(16) float g_pacc[2*NBH*SS*DH];
__device__ __align__(16) float g_pl[2*NBH*SS];

__device__ __forceinline__ float ex2(float x){
    float y; asm("ex2.approx.f32 %0, %1;" : "=f"(y) : "f"(x)); return y;
}
__device__ __forceinline__ u64 pk2(float x, float y){
    u64 r; asm("mov.b64 %0, {%1, %2};" : "=l"(r) : "f"(x), "f"(y)); return r;
}
__device__ __forceinline__ float2 upk2(u64 a){
    float2 r; asm("mov.b64 {%0, %1}, %2;" : "=f"(r.x), "=f"(r.y) : "l"(a)); return r;
}
__device__ __forceinline__ u64 fma2(u64 a, u64 b, u64 c){
    u64 d; asm("fma.rn.f32x2 %0, %1, %2, %3;" : "=l"(d) : "l"(a), "l"(b), "l"(c)); return d;
}

// ---------------- Kernel 1: LN1 + QKV, register-tiled 4 tokens x 8 outputs ----------------
// grid 512, block 240 threads. 64 tokens/block. tg = tid%16 (token group of 4),
// og = tid/16 (output group of 8). LDS:FMA = 1:4.
__global__ void __launch_bounds__(240) k_ln_qkv(
    const float* __restrict__ x,
    const float* __restrict__ g1, const float* __restrict__ b1,
    const float* __restrict__ Wq, const float* __restrict__ bq,
    const float* __restrict__ Wk, const float* __restrict__ bk,
    const float* __restrict__ Wv, const float* __restrict__ bv)
{
    __shared__ __align__(16) float Ws[HID*120];   // [i][o]: 0-39 q, 40-79 k, 80-119 v
    __shared__ __align__(16) float bs[120];
    __shared__ __align__(16) u64  hd[HID*64];     // duplicated (h,h), [i][tok]
    __shared__ __align__(16) float qkv_s[64*120]; // bounce buffer [tok][o]
    __shared__ float g1s[HID], b1s_[HID];

    const int tid = threadIdx.x;
    const int b   = blockIdx.x >> 3;
    const int s0  = (blockIdx.x & 7) << 6;
    const int t0  = blockIdx.x * 64;

    // stage weights (vectorized, coalesced)
    for (int idx = tid; idx < 400; idx += 240) {
        int i = idx / 10, c = idx % 10;
        *(float4*)&Ws[i*120 +      c*4] = *(const float4*)&Wq[i*40 + c*4];
        *(float4*)&Ws[i*120 + 40 + c*4] = *(const float4*)&Wk[i*40 + c*4];
        *(float4*)&Ws[i*120 + 80 + c*4] = *(const float4*)&Wv[i*40 + c*4];
    }
    if (tid < HID) {
        bs[tid] = bq[tid]; bs[40+tid] = bk[tid]; bs[80+tid] = bv[tid];
        g1s[tid] = g1[tid]; b1s_[tid] = b1[tid];
    }
    __syncthreads();   // g1s/b1s_ ready for LN phase

    // LN: threads 0-63, one token each, direct GMEM reads (L2-resident)
    if (tid < 64) {
        const float4* xr = (const float4*)(x + (size_t)(t0 + tid)*HID);
        float xv[HID]; float s1 = 0.f, s2 = 0.f;
#pragma unroll
        for (int i4 = 0; i4 < 10; i4++) {
            float4 v = xr[i4];
            xv[4*i4]=v.x; xv[4*i4+1]=v.y; xv[4*i4+2]=v.z; xv[4*i4+3]=v.w;
            s1 += v.x + v.y + v.z + v.w;
            s2 += v.x*v.x + v.y*v.y + v.z*v.z + v.w*v.w;
        }
        float mu = s1 * (1.f/HID);
        float var = s2 * (1.f/HID) - mu*mu;
        float rs = rsqrtf(var + 1e-5f);
#pragma unroll
        for (int i = 0; i < HID; i++) {
            float hv = (xv[i] - mu)*rs*g1s[i] + b1s_[i];
            hd[i*64 + tid] = pk2(hv, hv);
        }
    }
    __syncthreads();

    // main GEMM: 4 tokens x 8 outputs per thread
    const int tg = tid & 15;
    const int og = tid / 16;          // 0..14
    const int tok0 = tg * 4;
    const int o0 = og * 8;

    u64 acc[4][4];
    {
        ulonglong2 b01 = *(const ulonglong2*)&bs[o0];
        ulonglong2 b23 = *(const ulonglong2*)&bs[o0+4];
        u64 bp[4] = {b01.x, b01.y, b23.x, b23.y};
#pragma unroll
        for (int j = 0; j < 4; j++)
#pragma unroll
            for (int p = 0; p < 4; p++) acc[j][p] = bp[p];
    }

#pragma unroll
    for (int i = 0; i < HID; i++) {
        ulonglong2 h01 = *(const ulonglong2*)&hd[i*64 + tok0];
        ulonglong2 h23 = *(const ulonglong2*)&hd[i*64 + tok0 + 2];
        ulonglong2 w01 = *(const ulonglong2*)&Ws[i*120 + o0];       // uniform -> broadcast
        ulonglong2 w23 = *(const ulonglong2*)&Ws[i*120 + o0 + 4];
        u64 hh[4] = {h01.x, h01.y, h23.x, h23.y};
        u64 ww[4] = {w01.x, w01.y, w23.x, w23.y};
#pragma unroll
        for (int j = 0; j < 4; j++) {
#pragma unroll
            for (int p = 0; p < 4; p++)
                acc[j][p] = fma2(hh[j], ww[p], acc[j][p]);
        }
    }

    // bounce to smem
#pragma unroll
    for (int j = 0; j < 4; j++)
#pragma unroll
        for (int p = 0; p < 4; p++)
            *(float2*)&qkv_s[(tok0 + j)*120 + o0 + 2*p] = upk2(acc[j][p]);
    __syncthreads();

    // coalesced stores: 12 segments (which,head) of 640 contiguous floats each
    for (int idx = tid; idx < 1920; idx += 240) {
        int seg = idx / 160, r = idx % 160;
        int which = seg >> 2, hh = seg & 3;
        int base = which*40 + hh*10;
        int l = r * 4;
        float4 v;
        v.x = qkv_s[(l/10)*120 + base + (l%10)]; l++;
        v.y = qkv_s[(l/10)*120 + base + (l%10)]; l++;
        v.z = qkv_s[(l/10)*120 + base + (l%10)]; l++;
        v.w = qkv_s[(l/10)*120 + base + (l%10)];
        float* dst = (which == 0) ? g_q : (which == 1) ? g_k : g_v;
        *(float4*)&dst[(((size_t)b*HEADS + hh)*SS + s0)*DH + r*4] = v;
    }
}

// ---------------- Kernel 2: attention, split-K, no-max softmax (R8) ----------------
__global__ void __launch_bounds__(128) k_attn()
{
    __shared__ __align__(16) float ks[KHALF*DH];
    __shared__ __align__(16) float vs[KHALF*DH];

    const int tid = threadIdx.x;
    const int blk = blockIdx.x;
    const int kh  = blk & 1;
    const int qh  = (blk >> 1) & 1;
    const int bh  = blk >> 2;

    const float4* kb = (const float4*)(g_k + (size_t)bh*SS*DH + kh*KHALF*DH);
    const float4* vb = (const float4*)(g_v + (size_t)bh*SS*DH + kh*KHALF*DH);
#pragma unroll
    for (int i = 0; i < KHALF*DH/4/128; i++) {
        ((float4*)ks)[tid + i*128] = kb[tid + i*128];
        ((float4*)vs)[tid + i*128] = vb[tid + i*128];
    }

    const int qA = qh*256 + tid;
    const int qB = qA + 128;
    const float scale = 0.316227766016838f * 1.44269504088896f; // 1/sqrt(DH)*log2e
    u64 qa[5], qb[5];
    {
        const float* pA = g_q + ((size_t)bh*SS + qA)*DH;
        const float* pB = g_q + ((size_t)bh*SS + qB)*DH;
#pragma unroll
        for (int j = 0; j < 5; j++) {
            qa[j] = pk2(pA[2*j]*scale, pA[2*j+1]*scale);
            qb[j] = pk2(pB[2*j]*scale, pB[2*j+1]*scale);
        }
    }
    __syncthreads();

    float lA = 0.f, lB = 0.f;
    u64 aA[5] = {0,0,0,0,0};
    u64 aB[5] = {0,0,0,0,0};

#pragma unroll 4
    for (int s = 0; s < KHALF; s++) {
        const u64* kk = (const u64*)&ks[s*DH];
        u64 k0=kk[0], k1=kk[1], k2=kk[2], k3=kk[3], k4=kk[4];
        u64 dA = 0ULL, dB = 0ULL;
        dA = fma2(qa[0],k0,dA); dB = fma2(qb[0],k0,dB);
        dA = fma2(qa[1],k1,dA); dB = fma2(qb[1],k1,dB);
        dA = fma2(qa[2],k2,dA); dB = fma2(qb[2],k2,dB);
        dA = fma2(qa[3],k3,dA); dB = fma2(qb[3],k3,dB);
        dA = fma2(qa[4],k4,dA); dB = fma2(qb[4],k4,dB);
        float2 fA = upk2(dA);
        float2 fB = upk2(dB);
        float pA = ex2(fA.x + fA.y);   // scores tiny: no max subtraction needed
        float pB = ex2(fB.x + fB.y);
        lA += pA; lB += pB;

        const u64* vv = (const u64*)&vs[s*DH];
        u64 v0=vv[0], v1=vv[1], v2=vv[2], v3=vv[3], v4=vv[4];
        u64 pA2 = pk2(pA, pA);
        u64 pB2 = pk2(pB, pB);
        aA[0]=fma2(pA2,v0,aA[0]); aB[0]=fma2(pB2,v0,aB[0]);
        aA[1]=fma2(pA2,v1,aA[1]); aB[1]=fma2(pB2,v1,aB[1]);
        aA[2]=fma2(pA2,v2,aA[2]); aB[2]=fma2(pB2,v2,aB[2]);
        aA[3]=fma2(pA2,v3,aA[3]); aB[3]=fma2(pB2,v3,aB[3]);
        aA[4]=fma2(pA2,v4,aA[4]); aB[4]=fma2(pB2,v4,aB[4]);
    }

    float* paccA = g_pacc + (((size_t)kh*NBH + bh)*SS + qA)*DH;
    float* paccB = g_pacc + (((size_t)kh*NBH + bh)*SS + qB)*DH;
#pragma unroll
    for (int j = 0; j < 5; j++) {
        *(float2*)&paccA[2*j] = upk2(aA[j]);
        *(float2*)&paccB[2*j] = upk2(aB[j]);
    }
    g_pl[((size_t)kh*NBH + bh)*SS + qA] = lA;
    g_pl[((size_t)kh*NBH + bh)*SS + qB] = lB;
}

// ---------------- Kernel 3: combine + Wo + residual + LN2 + FFN + residual (R8) ----------------
__global__ void __launch_bounds__(128) k_out_ffn(
    const float* __restrict__ x,
    const float* __restrict__ Wo, const float* __restrict__ bo,
    const float* __restrict__ g2, const float* __restrict__ b2g,
    const float* __restrict__ W1, const float* __restrict__ b1f,
    const float* __restrict__ W2, const float* __restrict__ b2f,
    float* __restrict__ out)
{
    __shared__ __align__(16) float Wos[HID*HID];
    __shared__ __align__(16) float W1s[HID*INTER];
    __shared__ __align__(16) float W2s[INTER*HID];
    __shared__ __align__(16) u64  cs[32*41];
    __shared__ __align__(16) float ao_s[32*HID];
    __shared__ __align__(16) u64  h2s[32*41];
    __shared__ __align__(16) float it_s[32*INTER];
    __shared__ float bos[HID], b1s[INTER], b2s[HID], g2s[HID], b2gs[HID];

    const int tid = threadIdx.x;
    for (int i = tid; i < HID*HID; i += 128)   Wos[i] = Wo[i];
    for (int i = tid; i < HID*INTER; i += 128) W1s[i] = W1[i];
    for (int i = tid; i < INTER*HID; i += 128) W2s[i] = W2[i];
    if (tid < HID)   { bos[tid] = bo[tid]; b2s[tid] = b2f[tid]; g2s[tid] = g2[tid]; b2gs[tid] = b2g[tid]; }
    if (tid < INTER) { b1s[tid] = b1f[tid]; }

    const int tok  = tid >> 2;
    const int part = tid & 3;
    const int t = blockIdx.x*32 + tok;
    const int b = t / SS, s = t % SS;
    const int base = part * 10;

    // combine split-K partials for head `part` of this token
    {
        const int bh = b*HEADS + part;
        const float* p0 = g_pacc + (((size_t)0*NBH + bh)*SS + s)*DH;
        const float* p1 = g_pacc + (((size_t)1*NBH + bh)*SS + s)*DH;
        float l = g_pl[((size_t)0*NBH + bh)*SS + s] + g_pl[((size_t)1*NBH + bh)*SS + s];
        float inv = 1.f / l;
#pragma unroll
        for (int j = 0; j < 5; j++) {
            float2 a0 = *(const float2*)&p0[2*j];
            float2 a1 = *(const float2*)&p1[2*j];
            float cx = (a0.x + a1.x) * inv;
            float cy = (a0.y + a1.y) * inv;
            cs[tok*41 + part*DH + 2*j]     = pk2(cx, cx);
            cs[tok*41 + part*DH + 2*j + 1] = pk2(cy, cy);
        }
    }
    __syncthreads();

    // ao[base..base+10) = ctx @ Wo + bo + x
    u64 acc[5];
#pragma unroll
    for (int j = 0; j < 5; j++) acc[j] = *(const u64*)&bos[base + 2*j];
#pragma unroll
    for (int i = 0; i < HID; i++) {
        u64 c2 = cs[tok*41 + i];
        const u64* wr = (const u64*)&Wos[i*HID + base];
#pragma unroll
        for (int j = 0; j < 5; j++) acc[j] = fma2(c2, wr[j], acc[j]);
    }
    float aoc[10];
#pragma unroll
    for (int j = 0; j < 5; j++) {
        float2 v = upk2(acc[j]);
        float2 xv = *(const float2*)&x[(size_t)t*HID + base + 2*j];
        aoc[2*j]   = v.x + xv.x;
        aoc[2*j+1] = v.y + xv.y;
        *(float2*)&ao_s[tok*HID + base + 2*j] = make_float2(aoc[2*j], aoc[2*j+1]);
    }
    __syncthreads();

    // LN2, single pass
    float s1 = 0.f, s2 = 0.f;
    {
        const float4* ar = (const float4*)&ao_s[tok*HID];
#pragma unroll
        for (int i4 = 0; i4 < 10; i4++) {
            float4 v = ar[i4];
            s1 += v.x + v.y + v.z + v.w;
            s2 += v.x*v.x + v.y*v.y + v.z*v.z + v.w*v.w;
        }
    }
    float mu = s1 * (1.f/HID);
    float var = s2 * (1.f/HID) - mu*mu;
    float rs = rsqrtf(var + 1e-5f);
#pragma unroll
    for (int i = base; i < base + 10; i++) {
        float hv = (ao_s[tok*HID + i] - mu)*rs*g2s[i] + b2gs[i];
        h2s[tok*41 + i] = pk2(hv, hv);
    }
    __syncthreads();

    // inter[ibase..ibase+5) = gelu(h2 @ W1 + b1)
    const int ibase = part * 5;
    {
        float it[5];
#pragma unroll
        for (int o = 0; o < 5; o++) it[o] = b1s[ibase + o];
#pragma unroll
        for (int i = 0; i < HID; i++) {
            float hi = *(const float*)&h2s[tok*41 + i];
            const float* wr = &W1s[i*INTER + ibase];
#pragma unroll
            for (int o = 0; o < 5; o++) it[o] = fmaf(hi, wr[o], it[o]);
        }
#pragma unroll
        for (int o = 0; o < 5; o++) {
            float z = it[o];
            it_s[tok*INTER + ibase + o] = 0.5f * z * (1.f + erff(z * 0.70710678118654752f));
        }
    }
    __syncthreads();

    // out[base..base+10) = inter @ W2 + b2 + ao
    u64 acc2[5];
#pragma unroll
    for (int j = 0; j < 5; j++) acc2[j] = *(const u64*)&b2s[base + 2*j];
#pragma unroll
    for (int i = 0; i < INTER; i++) {
        float iv = it_s[tok*INTER + i];
        u64 i2 = pk2(iv, iv);
        const u64* wr = (const u64*)&W2s[i*HID + base];
#pragma unroll
        for (int j = 0; j < 5; j++) acc2[j] = fma2(i2, wr[j], acc2[j]);
    }
#pragma unroll
    for (int j = 0; j < 5; j++) {
        float2 v = upk2(acc2[j]);
        float2 o; o.x = v.x + aoc[2*j]; o.y = v.y + aoc[2*j+1];
        *(float2*)&out[(size_t)t*HID + base + 2*j] = o;
    }
}

extern "C" void kernel_launch(void* const* d_in, const int* in_sizes, int n_in,
                              void* d_out, int out_size)
{
    const float* x    = (const float*)d_in[0];
    const float* ln1g = (const float*)d_in[1];
    const float* ln1b = (const float*)d_in[2];
    const float* Wq   = (const float*)d_in[3];
    const float* bq   = (const float*)d_in[4];
    const float* Wk   = (const float*)d_in[5];
    const float* bk   = (const float*)d_in[6];
    const float* Wv   = (const float*)d_in[7];
    const float* bv   = (const float*)d_in[8];
    const float* Wo   = (const float*)d_in[9];
    const float* bo   = (const float*)d_in[10];
    const float* ln2g = (const float*)d_in[11];
    const float* ln2b = (const float*)d_in[12];
    const float* W1   = (const float*)d_in[13];
    const float* b1   = (const float*)d_in[14];
    const float* W2   = (const float*)d_in[15];
    const float* b2   = (const float*)d_in[16];
    float* out = (float*)d_out;

    k_ln_qkv<<<TT/64, 240>>>(x, ln1g, ln1b, Wq, bq, Wk, bk, Wv, bv);
    k_attn<<<NBH*4, 128>>>();
    k_out_ffn<<<TT/32, 128>>>(x, Wo, bo, ln2g, ln2b, W1, b1, W2, b2, out);
}